// round 2
// baseline (speedup 1.0000x reference)
#include <cuda_runtime.h>
#include <cuda_bf16.h>
#include <cstdint>
#include <cstddef>

// Problem dims (fixed by the benchmark)
#define MDIM 8192   // B*S = 4*2048
#define DDIM 2048   // model dim
#define HDIM 8192   // hidden = 4*D

// ---------------- device scratch (no allocation allowed) ----------------
__device__ float          g_h  [(size_t)MDIM * HDIM];   // fp32 pre-activation (x@q1)
__device__ __nv_bfloat16  g_hq [(size_t)MDIM * HDIM];   // integer k in bf16
__device__ __nv_bfloat16  g_x1 [(size_t)MDIM * DDIM];   // bf16 split hi
__device__ __nv_bfloat16  g_x2 [(size_t)MDIM * DDIM];   // bf16 split mid
__device__ __nv_bfloat16  g_x3 [(size_t)MDIM * DDIM];   // bf16 split lo
__device__ __nv_bfloat16  g_w1q[(size_t)DDIM * HDIM];   // q1, layout [D,H] = [K,N]
__device__ __nv_bfloat16  g_w2q[(size_t)HDIM * DDIM];   // q2^T, layout [H,D] = [K,N]
__device__ float          g_xmax[MDIM];
__device__ double         g_part[2][1024];
__device__ float          g_scales[4];  // {s1, s2, s2/255, -}

// ---------------- small helpers ----------------
__device__ __forceinline__ void cp_async16(uint32_t dst, const void* src) {
    asm volatile("cp.async.cg.shared.global [%0], [%1], 16;\n" :: "r"(dst), "l"(src) : "memory");
}
__device__ __forceinline__ void ldsm_x4(uint32_t &r0, uint32_t &r1, uint32_t &r2, uint32_t &r3, uint32_t addr) {
    asm volatile("ldmatrix.sync.aligned.m8n8.x4.shared.b16 {%0,%1,%2,%3}, [%4];"
                 : "=r"(r0), "=r"(r1), "=r"(r2), "=r"(r3) : "r"(addr));
}
__device__ __forceinline__ void ldsm_x4_t(uint32_t &r0, uint32_t &r1, uint32_t &r2, uint32_t &r3, uint32_t addr) {
    asm volatile("ldmatrix.sync.aligned.m8n8.x4.trans.shared.b16 {%0,%1,%2,%3}, [%4];"
                 : "=r"(r0), "=r"(r1), "=r"(r2), "=r"(r3) : "r"(addr));
}
__device__ __forceinline__ void mma16816(float* c, const uint32_t* a, const uint32_t* b) {
    asm volatile("mma.sync.aligned.m16n8k16.row.col.f32.bf16.bf16.f32 "
                 "{%0,%1,%2,%3}, {%4,%5,%6,%7}, {%8,%9}, {%0,%1,%2,%3};"
                 : "+f"(c[0]), "+f"(c[1]), "+f"(c[2]), "+f"(c[3])
                 : "r"(a[0]), "r"(a[1]), "r"(a[2]), "r"(a[3]), "r"(b[0]), "r"(b[1]));
}

// ---------------- scale reduction (deterministic, two-stage, fp64) ----------------
__global__ void reduce_abs_partial(const float* __restrict__ a, const float* __restrict__ b,
                                   double* __restrict__ part, int n) {
    const float* src = blockIdx.y ? b : a;
    double* dst = part + (size_t)blockIdx.y * 1024;
    double s = 0.0;
    for (int i = blockIdx.x * 256 + threadIdx.x; i < n; i += 256 * 1024)
        s += (double)fabsf(src[i]);
    __shared__ double sm[256];
    sm[threadIdx.x] = s; __syncthreads();
    for (int t = 128; t > 0; t >>= 1) {
        if (threadIdx.x < t) sm[threadIdx.x] += sm[threadIdx.x + t];
        __syncthreads();
    }
    if (threadIdx.x == 0) dst[blockIdx.x] = sm[0];
}

__global__ void reduce_final(const double* __restrict__ part, float* __restrict__ scales, int n_elems) {
    __shared__ double sm[256];
    for (int y = 0; y < 2; y++) {
        double s = 0.0;
        for (int i = threadIdx.x; i < 1024; i += 256) s += part[(size_t)y * 1024 + i];
        sm[threadIdx.x] = s; __syncthreads();
        for (int t = 128; t > 0; t >>= 1) {
            if (threadIdx.x < t) sm[threadIdx.x] += sm[threadIdx.x + t];
            __syncthreads();
        }
        if (threadIdx.x == 0) {
            float sc = fmaxf((float)(sm[0] / (double)n_elems), 1e-5f);
            scales[y] = sc;
            if (y == 1) scales[2] = sc / 255.0f;
        }
        __syncthreads();
    }
}

// ---------------- x -> 3-way bf16 split ----------------
__global__ void split_x(const float* __restrict__ x,
                        __nv_bfloat16* __restrict__ x1,
                        __nv_bfloat16* __restrict__ x2,
                        __nv_bfloat16* __restrict__ x3, int n) {
    int i = blockIdx.x * 256 + threadIdx.x;
    if (i >= n) return;
    float f = x[i];
    __nv_bfloat16 b1 = __float2bfloat16(f);
    float r1 = f - __bfloat162float(b1);
    __nv_bfloat16 b2 = __float2bfloat16(r1);
    float r2 = r1 - __bfloat162float(b2);
    __nv_bfloat16 b3 = __float2bfloat16(r2);
    x1[i] = b1; x2[i] = b2; x3[i] = b3;
}

// ---------------- weight quantization ----------------
__global__ void pack_w1(const float* __restrict__ w, __nv_bfloat16* __restrict__ out,
                        const float* __restrict__ scales, int n) {
    int i = blockIdx.x * 256 + threadIdx.x;
    if (i >= n) return;
    float s = scales[0];
    float q = fminf(fmaxf(rintf(w[i] / s), -1.0f), 1.0f);
    out[i] = __float2bfloat16(q);
}

// c_proj [D, H] -> quantize + transpose -> [H, D]
__global__ void pack_w2T(const float* __restrict__ w, __nv_bfloat16* __restrict__ out,
                         const float* __restrict__ scales) {
    __shared__ float tile[32][33];
    int h0 = blockIdx.x * 32, d0 = blockIdx.y * 32;
    int tx = threadIdx.x, ty = threadIdx.y;  // 32 x 8
    #pragma unroll
    for (int j = 0; j < 32; j += 8)
        tile[ty + j][tx] = w[(size_t)(d0 + ty + j) * HDIM + h0 + tx];
    __syncthreads();
    float s = scales[1];
    #pragma unroll
    for (int j = 0; j < 32; j += 8) {
        float q = fminf(fmaxf(rintf(tile[tx][ty + j] / s), -1.0f), 1.0f);
        out[(size_t)(h0 + ty + j) * DDIM + d0 + tx] = __float2bfloat16(q);
    }
}

// ---------------- relu^2 + rowmax + 8-bit requant ----------------
__global__ void act_quant(const float* __restrict__ h, __nv_bfloat16* __restrict__ hq,
                          float* __restrict__ xmax_out, const float* __restrict__ scales) {
    int row = blockIdx.x;
    int tid = threadIdx.x;
    const float s1 = scales[0];
    const float* hr = h + (size_t)row * HDIM;
    float pv[32];
    float lmax = 0.0f;
    #pragma unroll
    for (int i = 0; i < 32; i++) {
        float t = s1 * hr[tid + i * 256];
        float p = (t > 0.0f) ? t * t : 0.0f;
        pv[i] = p;
        lmax = fmaxf(lmax, p);
    }
    __shared__ float red[256];
    red[tid] = lmax; __syncthreads();
    for (int t = 128; t > 0; t >>= 1) {
        if (tid < t) red[tid] = fmaxf(red[tid], red[tid + t]);
        __syncthreads();
    }
    float xm = fmaxf(red[0], 1e-5f);
    if (tid == 0) xmax_out[row] = xm;
    __nv_bfloat16* hqr = hq + (size_t)row * HDIM;
    #pragma unroll
    for (int i = 0; i < 32; i++) {
        float k = rintf((pv[i] / xm) * 255.0f);   // matches jnp: round(x/xmax*255)
        hqr[tid + i * 256] = __float2bfloat16(k); // k in [0,255] -> exact in bf16
    }
}

// ---------------- bf16 GEMM: C[M,N] (+)= A[M,K] @ B[K,N], fp32 accum ----------------
// A row-major [M,K]; B row-major [K,N] (n-contiguous); epilogue optional scales.
#define BM 128
#define BN 128
#define BK 32
#define A_ST 40    // padded row pitch (elements) -> 80B, conflict-free ldmatrix
#define B_ST 136   // padded row pitch (elements) -> 272B, conflict-free ldmatrix

__global__ __launch_bounds__(256, 2) void gemm_bf16_tn(
    const __nv_bfloat16* __restrict__ A,
    const __nv_bfloat16* __restrict__ B,
    float* __restrict__ C,
    int M, int N, int K, int accumulate,
    const float* __restrict__ gscale,
    const float* __restrict__ rowscale)
{
    __shared__ __align__(16) __nv_bfloat16 As[2][BM * A_ST];
    __shared__ __align__(16) __nv_bfloat16 Bs[2][BK * B_ST];

    const int tid  = threadIdx.x;
    const int lane = tid & 31;
    const int wid  = tid >> 5;
    const int bm = blockIdx.y * BM;
    const int bn = blockIdx.x * BN;
    const int wm = (wid >> 2) * 64;   // 2 warps along M
    const int wn = (wid & 3) * 32;    // 4 warps along N

    float acc[4][4][4];
    #pragma unroll
    for (int i = 0; i < 4; i++)
        #pragma unroll
        for (int j = 0; j < 4; j++)
            #pragma unroll
            for (int r = 0; r < 4; r++) acc[i][j][r] = 0.0f;

    const int KT = K / BK;

    auto load_tile = [&](int stage, int kt) {
        const int k0 = kt * BK;
        #pragma unroll
        for (int i = 0; i < 2; i++) {
            int chunk = tid + i * 256;           // 512 chunks of 16B for A (128x32)
            int r = chunk >> 2, c = (chunk & 3) * 8;
            uint32_t dst = (uint32_t)__cvta_generic_to_shared(&As[stage][r * A_ST + c]);
            cp_async16(dst, A + (size_t)(bm + r) * K + k0 + c);
        }
        #pragma unroll
        for (int i = 0; i < 2; i++) {
            int chunk = tid + i * 256;           // 512 chunks of 16B for B (32x128)
            int r = chunk >> 4, c = (chunk & 15) * 8;
            uint32_t dst = (uint32_t)__cvta_generic_to_shared(&Bs[stage][r * B_ST + c]);
            cp_async16(dst, B + (size_t)(k0 + r) * N + bn + c);
        }
    };

    auto compute_tile = [&](int stage) {
        uint32_t a_base = (uint32_t)__cvta_generic_to_shared(&As[stage][0]);
        uint32_t b_base = (uint32_t)__cvta_generic_to_shared(&Bs[stage][0]);
        #pragma unroll
        for (int kh = 0; kh < 2; kh++) {
            uint32_t afr[4][4];
            #pragma unroll
            for (int im = 0; im < 4; im++) {
                int row = wm + im * 16 + (lane & 15);
                int col = kh * 16 + (lane >> 4) * 8;
                ldsm_x4(afr[im][0], afr[im][1], afr[im][2], afr[im][3],
                        a_base + (uint32_t)(row * A_ST + col) * 2u);
            }
            uint32_t bfr[4][2];
            #pragma unroll
            for (int jp = 0; jp < 2; jp++) {
                int mtx  = lane >> 3;
                int krow = kh * 16 + (lane & 7) + (mtx & 1) * 8;
                int ncol = wn + jp * 16 + (mtx >> 1) * 8;
                uint32_t r0, r1, r2, r3;
                ldsm_x4_t(r0, r1, r2, r3, b_base + (uint32_t)(krow * B_ST + ncol) * 2u);
                bfr[jp * 2][0] = r0; bfr[jp * 2][1] = r1;
                bfr[jp * 2 + 1][0] = r2; bfr[jp * 2 + 1][1] = r3;
            }
            #pragma unroll
            for (int im = 0; im < 4; im++)
                #pragma unroll
                for (int jn = 0; jn < 4; jn++)
                    mma16816(acc[im][jn], afr[im], bfr[jn]);
        }
    };

    load_tile(0, 0);
    asm volatile("cp.async.commit_group;\n" ::: "memory");

    for (int kt = 0; kt < KT; kt++) {
        const int cur = kt & 1;
        if (kt + 1 < KT) {
            load_tile(cur ^ 1, kt + 1);
            asm volatile("cp.async.commit_group;\n" ::: "memory");
            asm volatile("cp.async.wait_group 1;\n" ::: "memory");
        } else {
            asm volatile("cp.async.wait_group 0;\n" ::: "memory");
        }
        __syncthreads();
        compute_tile(cur);
        __syncthreads();
    }

    // epilogue
    float fac = gscale ? *gscale : 1.0f;
    const int g = lane >> 2, tg = lane & 3;
    #pragma unroll
    for (int im = 0; im < 4; im++) {
        int r0 = bm + wm + im * 16 + g;
        int r1 = r0 + 8;
        float f0 = fac, f1 = fac;
        if (rowscale) { f0 *= rowscale[r0]; f1 *= rowscale[r1]; }
        #pragma unroll
        for (int jn = 0; jn < 4; jn++) {
            int c = bn + wn + jn * 8 + tg * 2;
            float* p0 = C + (size_t)r0 * N + c;
            float* p1 = C + (size_t)r1 * N + c;
            float v0 = acc[im][jn][0] * f0, v1 = acc[im][jn][1] * f0;
            float v2 = acc[im][jn][2] * f1, v3 = acc[im][jn][3] * f1;
            if (accumulate) { v0 += p0[0]; v1 += p0[1]; v2 += p1[0]; v3 += p1[1]; }
            p0[0] = v0; p0[1] = v1; p1[0] = v2; p1[1] = v3;
        }
    }
}

// ---------------- host launcher ----------------
extern "C" void kernel_launch(void* const* d_in, const int* in_sizes, int n_in,
                              void* d_out, int out_size) {
    const float* x      = (const float*)d_in[0];
    const float* c_fc   = (const float*)d_in[1];
    const float* c_proj = (const float*)d_in[2];
    float* out = (float*)d_out;

    float *p_h, *p_xmax, *p_scales;
    double* p_part;
    __nv_bfloat16 *p_hq, *p_x1, *p_x2, *p_x3, *p_w1q, *p_w2q;
    cudaGetSymbolAddress((void**)&p_h,      g_h);
    cudaGetSymbolAddress((void**)&p_hq,     g_hq);
    cudaGetSymbolAddress((void**)&p_x1,     g_x1);
    cudaGetSymbolAddress((void**)&p_x2,     g_x2);
    cudaGetSymbolAddress((void**)&p_x3,     g_x3);
    cudaGetSymbolAddress((void**)&p_w1q,    g_w1q);
    cudaGetSymbolAddress((void**)&p_w2q,    g_w2q);
    cudaGetSymbolAddress((void**)&p_xmax,   g_xmax);
    cudaGetSymbolAddress((void**)&p_part,   g_part);
    cudaGetSymbolAddress((void**)&p_scales, g_scales);

    const int n_w = DDIM * HDIM;        // 16,777,216
    const int n_x = MDIM * DDIM;        // 16,777,216

    // 1) weight scales (deterministic fp64 two-stage reduction)
    reduce_abs_partial<<<dim3(1024, 2), 256>>>(c_fc, c_proj, p_part, n_w);
    reduce_final<<<1, 256>>>(p_part, p_scales, n_w);

    // 2) activation split + weight quantization
    split_x<<<n_x / 256, 256>>>(x, p_x1, p_x2, p_x3, n_x);
    pack_w1<<<n_w / 256, 256>>>(c_fc, p_w1q, p_scales, n_w);
    pack_w2T<<<dim3(HDIM / 32, DDIM / 32), dim3(32, 8)>>>(c_proj, p_w2q, p_scales);

    // 3) GEMM1: h = (x1 + x2 + x3) @ q1   (3-way bf16 split for ~fp32 accuracy)
    gemm_bf16_tn<<<dim3(HDIM / BN, MDIM / BM), 256>>>(p_x1, p_w1q, p_h, MDIM, HDIM, DDIM, 0, nullptr, nullptr);
    gemm_bf16_tn<<<dim3(HDIM / BN, MDIM / BM), 256>>>(p_x2, p_w1q, p_h, MDIM, HDIM, DDIM, 1, nullptr, nullptr);
    gemm_bf16_tn<<<dim3(HDIM / BN, MDIM / BM), 256>>>(p_x3, p_w1q, p_h, MDIM, HDIM, DDIM, 1, nullptr, nullptr);

    // 4) relu^2 + per-row max + 8-bit requant (k stored exactly in bf16)
    act_quant<<<MDIM, 256>>>(p_h, p_hq, p_xmax, p_scales);

    // 5) GEMM2: out = hq @ q2^T, scaled by s2*xmax[m]/255 (exact integer math in bf16 MMA)
    gemm_bf16_tn<<<dim3(DDIM / BN, MDIM / BM), 256>>>(p_hq, p_w2q, out, MDIM, DDIM, HDIM, 0,
                                                      p_scales + 2, p_xmax);
}